// round 1
// baseline (speedup 1.0000x reference)
#include <cuda_runtime.h>
#include <math.h>

// SenseEmbedding:
//  x:   [16384, 12] int32   (d_in[0])  -- [w0, w1, ctx0..ctx9]
//  W_g: [100000, 128] f32   (d_in[1])
//  W_s: [100000, 8, 128] f32 (d_in[2])
//  out: [16384, 1] f32
//
// One warp per row. Lane l owns float4 elements [4l, 4l+4) of the 128-dim
// vectors, so every embedding-row gather is one fully coalesced 512B access.

#define CTX 10
#define NUM_SENSES 8
#define VEC4 32  // 128 floats = 32 float4 per row

__global__ void __launch_bounds__(256, 8)
sense_embedding_kernel(const int* __restrict__ x,
                       const float4* __restrict__ Wg,
                       const float4* __restrict__ Ws,
                       float* __restrict__ out,
                       int batch)
{
    int warp = (blockIdx.x * blockDim.x + threadIdx.x) >> 5;
    int lane = threadIdx.x & 31;
    if (warp >= batch) return;

    const int* xr = x + (size_t)warp * (2 + CTX);
    int w0 = __ldg(&xr[0]);
    int w1 = __ldg(&xr[1]);

    // ---- sum_context: sum of 10 gathered W_g rows (lane-sliced float4) ----
    float4 acc = make_float4(0.f, 0.f, 0.f, 0.f);
    int toks[CTX];
#pragma unroll
    for (int i = 0; i < CTX; i++) toks[i] = __ldg(&xr[2 + i]);
#pragma unroll
    for (int i = 0; i < CTX; i++) {
        float4 v = __ldg(&Wg[(size_t)toks[i] * VEC4 + lane]);
        acc.x += v.x; acc.y += v.y; acc.z += v.z; acc.w += v.w;
    }

    // ---- load all 8 sense vectors, per-lane partial dot with sum_context ----
    const float4* ws_row = Ws + (size_t)w0 * (NUM_SENSES * VEC4);
    float4 sv[NUM_SENSES];
    float partial[NUM_SENSES];
#pragma unroll
    for (int s = 0; s < NUM_SENSES; s++) {
        sv[s] = __ldg(&ws_row[s * VEC4 + lane]);
        partial[s] = sv[s].x * acc.x + sv[s].y * acc.y
                   + sv[s].z * acc.z + sv[s].w * acc.w;
    }

    // ---- warp-reduce each score, argmax (first max wins, like jnp.argmax) ----
    float best = -INFINITY;
    int bestk = 0;
#pragma unroll
    for (int s = 0; s < NUM_SENSES; s++) {
        float p = partial[s];
        p += __shfl_xor_sync(0xffffffffu, p, 16);
        p += __shfl_xor_sync(0xffffffffu, p, 8);
        p += __shfl_xor_sync(0xffffffffu, p, 4);
        p += __shfl_xor_sync(0xffffffffu, p, 2);
        p += __shfl_xor_sync(0xffffffffu, p, 1);
        if (p > best) { best = p; bestk = s; }  // uniform across lanes
    }

    // ---- dot(chosen sense, W_g[w1]) ----
    float4 tv = __ldg(&Wg[(size_t)w1 * VEC4 + lane]);
    float4 ch;
    // bestk is warp-uniform; select without spilling sv[] to local memory.
    ch = sv[0];
#pragma unroll
    for (int s = 1; s < NUM_SENSES; s++)
        if (s == bestk) ch = sv[s];

    float d = ch.x * tv.x + ch.y * tv.y + ch.z * tv.z + ch.w * tv.w;
    d += __shfl_xor_sync(0xffffffffu, d, 16);
    d += __shfl_xor_sync(0xffffffffu, d, 8);
    d += __shfl_xor_sync(0xffffffffu, d, 4);
    d += __shfl_xor_sync(0xffffffffu, d, 2);
    d += __shfl_xor_sync(0xffffffffu, d, 1);

    if (lane == 0)
        out[warp] = 1.0f / (1.0f + __expf(-d));
}

extern "C" void kernel_launch(void* const* d_in, const int* in_sizes, int n_in,
                              void* d_out, int out_size)
{
    const int*    x  = (const int*)d_in[0];
    const float4* Wg = (const float4*)d_in[1];
    const float4* Ws = (const float4*)d_in[2];
    float* out = (float*)d_out;

    int batch = in_sizes[0] / (2 + CTX);   // 16384
    int threads = 256;                      // 8 warps/block
    int blocks = (batch * 32 + threads - 1) / threads;
    sense_embedding_kernel<<<blocks, threads>>>(x, Wg, Ws, out, batch);
}

// round 2
// speedup vs baseline: 2.3529x; 2.3529x over previous
#include <cuda_runtime.h>
#include <math.h>

// SenseEmbedding:
//  x:   [16384, 12] int32   (d_in[0])  -- [w0, w1, ctx0..ctx9]
//  W_g: [100000, 128] f32   (d_in[1])
//  W_s: [100000, 8, 128] f32 (d_in[2])
//  out: [16384, 1] f32
//
// One warp per row; lane l owns float4 slice [4l,4l+4) -> every row gather is
// one coalesced 512B access. W_s is streamed with evict-first (.cs) so its
// 62MB one-shot stream does not evict the hot 51MB W_g table from L2.

#define CTX 10
#define NUM_SENSES 8
#define VEC4 32  // 128 floats = 32 float4

__global__ void __launch_bounds__(256, 8)
sense_embedding_kernel(const int4* __restrict__ x4,
                       const float4* __restrict__ Wg,
                       const float4* __restrict__ Ws,
                       float* __restrict__ out,
                       int batch)
{
    int warp = (blockIdx.x * blockDim.x + threadIdx.x) >> 5;
    int lane = threadIdx.x & 31;
    if (warp >= batch) return;

    // x row = 12 ints = 3 x int4 (48B, 16B-aligned per row)
    const int4* xr = x4 + (size_t)warp * 3;
    int4 xa = __ldg(&xr[0]);
    int4 xb = __ldg(&xr[1]);
    int4 xc = __ldg(&xr[2]);
    int w0 = xa.x, w1 = xa.y;
    int toks[CTX] = { xa.z, xa.w, xb.x, xb.y, xb.z, xb.w, xc.x, xc.y, xc.z, xc.w };

    // ---- sum_context: 10 gathered W_g rows (cached; table is L2-resident) ----
    float4 acc = make_float4(0.f, 0.f, 0.f, 0.f);
#pragma unroll
    for (int i = 0; i < CTX; i++) {
        float4 v = __ldg(&Wg[(size_t)toks[i] * VEC4 + lane]);
        acc.x += v.x; acc.y += v.y; acc.z += v.z; acc.w += v.w;
    }

    // ---- scores: stream all 8 sense vectors with evict-first, keep only dots ----
    const float4* ws_row = Ws + (size_t)w0 * (NUM_SENSES * VEC4) + lane;
    float partial[NUM_SENSES];
#pragma unroll
    for (int s = 0; s < NUM_SENSES; s++) {
        float4 v = __ldcs(&ws_row[s * VEC4]);
        partial[s] = v.x * acc.x + v.y * acc.y + v.z * acc.z + v.w * acc.w;
    }

    // ---- warp-reduce each score; argmax with first-max tie-break ----
    float best = -INFINITY;
    int bestk = 0;
#pragma unroll
    for (int s = 0; s < NUM_SENSES; s++) {
        float p = partial[s];
        p += __shfl_xor_sync(0xffffffffu, p, 16);
        p += __shfl_xor_sync(0xffffffffu, p, 8);
        p += __shfl_xor_sync(0xffffffffu, p, 4);
        p += __shfl_xor_sync(0xffffffffu, p, 2);
        p += __shfl_xor_sync(0xffffffffu, p, 1);
        if (p > best) { best = p; bestk = s; }  // warp-uniform
    }

    // ---- reload only the chosen sense (hits L1/L2), dot with W_g[w1] ----
    float4 ch = __ldg(&ws_row[bestk * VEC4]);
    float4 tv = __ldg(&Wg[(size_t)w1 * VEC4 + lane]);

    float d = ch.x * tv.x + ch.y * tv.y + ch.z * tv.z + ch.w * tv.w;
    d += __shfl_xor_sync(0xffffffffu, d, 16);
    d += __shfl_xor_sync(0xffffffffu, d, 8);
    d += __shfl_xor_sync(0xffffffffu, d, 4);
    d += __shfl_xor_sync(0xffffffffu, d, 2);
    d += __shfl_xor_sync(0xffffffffu, d, 1);

    if (lane == 0)
        out[warp] = 1.0f / (1.0f + __expf(-d));
}

extern "C" void kernel_launch(void* const* d_in, const int* in_sizes, int n_in,
                              void* d_out, int out_size)
{
    const int4*   x  = (const int4*)d_in[0];
    const float4* Wg = (const float4*)d_in[1];
    const float4* Ws = (const float4*)d_in[2];
    float* out = (float*)d_out;

    int batch = in_sizes[0] / (2 + CTX);   // 16384
    int threads = 256;                      // 8 warps/block
    int blocks = (batch * 32 + threads - 1) / threads;
    sense_embedding_kernel<<<blocks, threads>>>(x, Wg, Ws, out, batch);
}